// round 12
// baseline (speedup 1.0000x reference)
#include <cuda_runtime.h>
#include <math.h>

#define BB   8192
#define TT   21
#define NTY  10
#define VT   5000

typedef unsigned long long ull;

// ---------------- device scratch ----------------
__device__ __align__(16) float g_tokproj[2][VT][96];
__device__ __align__(16) float g_holeproj[2][96];
__device__ __align__(16) float g_tmax[21][32][BB];
__device__ __align__(16) float g_gx0[2][21][96][BB];
__device__ __align__(16) float g_y0[21][64][BB];
__device__ __align__(16) float g_gx1[2][21][96][BB];
__device__ int   g_mask_kind;

// ---------------- packed f32x2 helpers ----------------
__device__ __forceinline__ ull pk2(float lo, float hi) {
    ull r; asm("mov.b64 %0, {%1,%2};" : "=l"(r) : "f"(lo), "f"(hi)); return r;
}
__device__ __forceinline__ ull bc2(float v) {
    ull r; asm("mov.b64 %0, {%1,%1};" : "=l"(r) : "f"(v)); return r;
}
__device__ __forceinline__ void upk2(ull v, float& lo, float& hi) {
    asm("mov.b64 {%0,%1}, %2;" : "=f"(lo), "=f"(hi) : "l"(v));
}
__device__ __forceinline__ ull fma2(ull a, ull b, ull c) {
    ull d; asm("fma.rn.f32x2 %0, %1, %2, %3;" : "=l"(d) : "l"(a), "l"(b), "l"(c)); return d;
}
__device__ __forceinline__ ull ld2(const float* p) { return *(const ull*)p; }
__device__ __forceinline__ void st2(float* p, ull v) { *(ull*)p = v; }

__device__ __forceinline__ float sigmoidf_(float x) {
    return __fdividef(1.0f, 1.0f + __expf(-x));
}
__device__ __forceinline__ float tanhf_(float x) {
    x = fminf(fmaxf(x, -15.0f), 15.0f);
    float e = __expf(2.0f * x);
    return __fdividef(e - 1.0f, e + 1.0f);
}

// ---------------- mask dtype detection ----------------
__global__ void k_detect(const unsigned char* __restrict__ m) {
    __shared__ int s_nonbin, s_off;
    if (threadIdx.x == 0) { s_nonbin = 0; s_off = 0; }
    __syncthreads();
    int nonbin = 0, off = 0;
    for (int i = threadIdx.x; i < 4096; i += blockDim.x) {
        unsigned char v = m[i];
        if (v > 1) nonbin = 1;
        if ((i & 3) != 0 && v == 1) off = 1;
    }
    if (nonbin) atomicOr(&s_nonbin, 1);
    if (off)    atomicOr(&s_off, 1);
    __syncthreads();
    if (threadIdx.x == 0)
        g_mask_kind = s_nonbin ? 2 : (s_off ? 1 : 0);
}

// ---------------- vocab / hole projection through layer0 x-rows ----------------
__global__ void k_tokproj(const float* __restrict__ te, const float* __restrict__ hole,
                          const float* __restrict__ gkf, const float* __restrict__ gbf,
                          const float* __restrict__ ckf, const float* __restrict__ cbf,
                          const float* __restrict__ gkb, const float* __restrict__ gbb,
                          const float* __restrict__ ckb, const float* __restrict__ cbb) {
    __shared__ float sx[160];
    int v = blockIdx.x;
    int tid = threadIdx.x;
    bool is_hole = (v == VT);
    int xl = is_hole ? 160 : 128;
    if (is_hole) { if (tid < 160) sx[tid] = hole[tid]; }
    else         { if (tid < 128) sx[tid] = te[v * 128 + tid]; }
    __syncthreads();
    int d = tid / 96, j = tid % 96;
    const float* gk = d ? gkb : gkf;
    const float* ck = d ? ckb : ckf;
    const float* gb = d ? gbb : gbf;
    const float* cb = d ? cbb : cbf;
    float acc = (j < 64) ? gb[j] : cb[j - 64];
    if (j < 64) {
        for (int k = 0; k < xl; k++) acc += sx[k] * gk[k * 64 + j];
    } else {
        int jj = j - 64;
        for (int k = 0; k < xl; k++) acc += sx[k] * ck[k * 32 + jj];
    }
    if (is_hole) g_holeproj[d][j] = acc;
    else         g_tokproj[d][v][j] = acc;
}

// ---------------- masked max over type embeddings ----------------
__global__ void k_typemax(const int* __restrict__ types_b, const void* __restrict__ mask_b,
                          const int* __restrict__ types_a, const void* __restrict__ mask_a,
                          const float* __restrict__ typ_emb) {
    int kg = threadIdx.x, lbv = threadIdx.y;
    int b = blockIdx.x * 32 + lbv;
    int p = blockIdx.y;
    int t = (p < 10) ? p : p + 1;
    const int*  types = (p < 10) ? types_b : types_a;
    const void* maskp = (p < 10) ? mask_b : mask_a;
    int pp = (p < 10) ? p : p - 10;
    int mk = g_mask_kind;
    int base = (b * NTY + pp) * NTY;
    int k0 = kg * 4;
    float m0 = -3.4e38f, m1 = -3.4e38f, m2 = -3.4e38f, m3 = -3.4e38f;
    #pragma unroll
    for (int nt = 0; nt < NTY; nt++) {
        int id = types[base + nt];
        bool valid;
        if (mk == 0)      valid = ((const int*)maskp)[base + nt] != 0;
        else if (mk == 1) valid = ((const unsigned char*)maskp)[base + nt] != 0;
        else              valid = ((const float*)maskp)[base + nt] != 0.0f;
        float pen = valid ? 0.0f : -1000.0f;
        float4 e = *(const float4*)(typ_emb + id * 32 + k0);
        m0 = fmaxf(m0, e.x + pen);
        m1 = fmaxf(m1, e.y + pen);
        m2 = fmaxf(m2, e.z + pen);
        m3 = fmaxf(m3, e.w + pen);
    }
    g_tmax[t][k0 + 0][b] = m0;
    g_tmax[t][k0 + 1][b] = m1;
    g_tmax[t][k0 + 2][b] = m2;
    g_tmax[t][k0 + 3][b] = m3;
}

// ---------------- layer0 x-projection (R7 form: staged gather, direct tmax ld2) ----------------
// grid (BB/64, 21, 2), block (32,8); thread handles b = base+2*lb, base+2*lb+1
__global__ __launch_bounds__(256) void k_x0(const int* __restrict__ tok_b, const int* __restrict__ tok_a,
                     const float* __restrict__ gkf, const float* __restrict__ ckf,
                     const float* __restrict__ gkb, const float* __restrict__ ckb) {
    int d = blockIdx.z, t = blockIdx.y;
    int lb = threadIdx.x, jg = threadIdx.y;
    int b0 = blockIdx.x * 64 + 2 * lb;
    __shared__ __align__(16) float sW[32][96];
    __shared__ float sX[64][97];
    __shared__ int   stok[64];
    const float* gk = d ? gkb : gkf;
    const float* ck = d ? ckb : ckf;
    int tid = jg * 32 + lb;
    for (int i = tid; i < 32 * 96; i += 256) {
        int k = i / 96, j = i % 96;
        sW[k][j] = (j < 64) ? gk[(128 + k) * 64 + j] : ck[(128 + k) * 32 + (j - 64)];
    }
    float* out = &g_gx0[d][t][0][0];
    int j0 = jg * 12;
    if (t == 10) {
        #pragma unroll
        for (int jj = 0; jj < 12; jj++)
            st2(&out[(size_t)(j0 + jj) * BB + b0], bc2(g_holeproj[d][j0 + jj]));
        return;
    }
    int pp = (t < 10) ? t : t - 11;
    if (tid < 64) {
        int bg = blockIdx.x * 64 + tid;
        stok[tid] = (t < 10) ? tok_b[bg * NTY + pp] : tok_a[bg * NTY + pp];
    }
    __syncthreads();
    // cooperative gather of tokproj rows
    for (int i = tid; i < 64 * 24; i += 256) {
        int row = i / 24, q = i - row * 24;
        float4 v = ((const float4*)&g_tokproj[d][stok[row]][0])[q];
        sX[row][q * 4 + 0] = v.x;
        sX[row][q * 4 + 1] = v.y;
        sX[row][q * 4 + 2] = v.z;
        sX[row][q * 4 + 3] = v.w;
    }
    __syncthreads();
    ull acc[12];
    #pragma unroll
    for (int jj = 0; jj < 12; jj++)
        acc[jj] = pk2(sX[2 * lb][j0 + jj], sX[2 * lb + 1][j0 + jj]);
    const float* tm = &g_tmax[t][0][0];
    #pragma unroll
    for (int k = 0; k < 32; k++) {
        ull tv = ld2(&tm[(size_t)k * BB + b0]);
        const float4* w4 = (const float4*)&sW[k][j0];
        float4 w0 = w4[0], w1 = w4[1], w2 = w4[2];
        acc[0]  = fma2(tv, bc2(w0.x), acc[0]);
        acc[1]  = fma2(tv, bc2(w0.y), acc[1]);
        acc[2]  = fma2(tv, bc2(w0.z), acc[2]);
        acc[3]  = fma2(tv, bc2(w0.w), acc[3]);
        acc[4]  = fma2(tv, bc2(w1.x), acc[4]);
        acc[5]  = fma2(tv, bc2(w1.y), acc[5]);
        acc[6]  = fma2(tv, bc2(w1.z), acc[6]);
        acc[7]  = fma2(tv, bc2(w1.w), acc[7]);
        acc[8]  = fma2(tv, bc2(w2.x), acc[8]);
        acc[9]  = fma2(tv, bc2(w2.y), acc[9]);
        acc[10] = fma2(tv, bc2(w2.z), acc[10]);
        acc[11] = fma2(tv, bc2(w2.w), acc[11]);
    }
    #pragma unroll
    for (int jj = 0; jj < 12; jj++)
        st2(&out[(size_t)(j0 + jj) * BB + b0], acc[jj]);
}

// ---------------- layer1 x-projection: 4 batch/thread, staged y, f32x2 ----------------
// grid (BB/128, 21, 2), block (32,8); thread handles b = base+4*lb .. +3
__global__ __launch_bounds__(256) void k_x1(const float* __restrict__ gkf, const float* __restrict__ gbf,
                     const float* __restrict__ ckf, const float* __restrict__ cbf,
                     const float* __restrict__ gkb, const float* __restrict__ gbb,
                     const float* __restrict__ ckb, const float* __restrict__ cbb) {
    int d = blockIdx.z, t = blockIdx.y;
    int lb = threadIdx.x, jg = threadIdx.y;
    int bb = blockIdx.x * 128;
    __shared__ __align__(16) float sW[64][96];
    __shared__ __align__(16) float sY[32][128];
    const float* gk = d ? gkb : gkf;
    const float* ck = d ? ckb : ckf;
    const float* gb = d ? gbb : gbf;
    const float* cb = d ? cbb : cbf;
    int tid = jg * 32 + lb;
    for (int i = tid; i < 64 * 96; i += 256) {
        int k = i / 96, j = i % 96;
        sW[k][j] = (j < 64) ? gk[k * 64 + j] : ck[k * 32 + (j - 64)];
    }
    int j0 = jg * 12;
    ull acc0[12], acc1[12];
    #pragma unroll
    for (int jj = 0; jj < 12; jj++) {
        int j = j0 + jj;
        ull bv = bc2((j < 64) ? gb[j] : cb[j - 64]);
        acc0[jj] = bv; acc1[jj] = bv;
    }
    const float* y = &g_y0[t][0][0] + bb;
    #pragma unroll
    for (int half = 0; half < 2; half++) {
        __syncthreads();
        // stage 32 k-rows x 128 b
        for (int i = tid; i < 1024; i += 256) {
            int k = i >> 5, c = i & 31;
            float4 v = *(const float4*)(y + (size_t)(half * 32 + k) * BB + c * 4);
            *(float4*)&sY[k][c * 4] = v;
        }
        __syncthreads();
        #pragma unroll 8
        for (int k = 0; k < 32; k++) {
            const ull* yp = (const ull*)&sY[k][4 * lb];
            ull y0v = yp[0], y1v = yp[1];
            const float4* w4 = (const float4*)&sW[half * 32 + k][j0];
            float4 w0 = w4[0], w1 = w4[1], w2 = w4[2];
            ull c0, c1, c2;
            c0 = bc2(w0.x); acc0[0]  = fma2(y0v, c0, acc0[0]);  acc1[0]  = fma2(y1v, c0, acc1[0]);
            c1 = bc2(w0.y); acc0[1]  = fma2(y0v, c1, acc0[1]);  acc1[1]  = fma2(y1v, c1, acc1[1]);
            c2 = bc2(w0.z); acc0[2]  = fma2(y0v, c2, acc0[2]);  acc1[2]  = fma2(y1v, c2, acc1[2]);
            c0 = bc2(w0.w); acc0[3]  = fma2(y0v, c0, acc0[3]);  acc1[3]  = fma2(y1v, c0, acc1[3]);
            c1 = bc2(w1.x); acc0[4]  = fma2(y0v, c1, acc0[4]);  acc1[4]  = fma2(y1v, c1, acc1[4]);
            c2 = bc2(w1.y); acc0[5]  = fma2(y0v, c2, acc0[5]);  acc1[5]  = fma2(y1v, c2, acc1[5]);
            c0 = bc2(w1.z); acc0[6]  = fma2(y0v, c0, acc0[6]);  acc1[6]  = fma2(y1v, c0, acc1[6]);
            c1 = bc2(w1.w); acc0[7]  = fma2(y0v, c1, acc0[7]);  acc1[7]  = fma2(y1v, c1, acc1[7]);
            c2 = bc2(w2.x); acc0[8]  = fma2(y0v, c2, acc0[8]);  acc1[8]  = fma2(y1v, c2, acc1[8]);
            c0 = bc2(w2.y); acc0[9]  = fma2(y0v, c0, acc0[9]);  acc1[9]  = fma2(y1v, c0, acc1[9]);
            c1 = bc2(w2.z); acc0[10] = fma2(y0v, c1, acc0[10]); acc1[10] = fma2(y1v, c1, acc1[10]);
            c2 = bc2(w2.w); acc0[11] = fma2(y0v, c2, acc0[11]); acc1[11] = fma2(y1v, c2, acc1[11]);
        }
    }
    float* out = &g_gx1[d][t][0][0] + bb + 4 * lb;
    #pragma unroll
    for (int jj = 0; jj < 12; jj++) {
        ull* o = (ull*)&out[(size_t)(j0 + jj) * BB];
        o[0] = acc0[jj];
        o[1] = acc1[jj];
    }
}

// ---------------- recurrent scan: prefetched gx, adjacent-pair b, optional direct output ----------------
// grid (BB/64, 2), block (32,8)
__global__ __launch_bounds__(256) void k_scan(const float* __restrict__ gx, float* __restrict__ y,
                       const float* __restrict__ gkf, const float* __restrict__ ckf,
                       const float* __restrict__ gkb, const float* __restrict__ ckb,
                       int hoff, int direct) {
    int d = blockIdx.y;
    int lb = threadIdx.x, jg = threadIdx.y;
    int b0 = blockIdx.x * 64 + 2 * lb;
    const float* gk = d ? gkb : gkf;
    const float* ck = d ? ckb : ckf;
    __shared__ __align__(16) float sWg[32][64];
    __shared__ __align__(16) float sWc[32][32];
    __shared__ ull sH[32][33];
    __shared__ ull sRH[32][33];
    __shared__ ull sU[32][33];
    int tid = jg * 32 + lb;
    for (int i = tid; i < 32 * 64; i += 256) { int k = i / 64, j = i % 64; sWg[k][j] = gk[(hoff + k) * 64 + j]; }
    for (int i = tid; i < 32 * 32; i += 256) { int k = i / 32, j = i % 32; sWc[k][j] = ck[(hoff + k) * 32 + j]; }
    for (int i = tid; i < 32 * 32; i += 256) { sH[i / 32][i % 32] = 0ULL; }
    __syncthreads();
    const float* gxd = gx + (size_t)d * TT * 96 * BB;
    int ycol = d ? 32 : 0;
    int j0 = jg * 8;
    int jc0 = jg * 4;
    // software pipeline: preload step 0's x-projections
    ull a[8], cc[4];
    {
        const float* gxt = gxd + (size_t)(d ? TT - 1 : 0) * 96 * BB;
        #pragma unroll
        for (int jj = 0; jj < 8; jj++) a[jj] = ld2(&gxt[(size_t)(j0 + jj) * BB + b0]);
        #pragma unroll
        for (int jj = 0; jj < 4; jj++) cc[jj] = ld2(&gxt[(size_t)(64 + jc0 + jj) * BB + b0]);
    }
    for (int s = 0; s < TT; s++) {
        int t = d ? (TT - 1 - s) : s;
        // ---- prefetch next step's gx into registers (independent of recurrence) ----
        ull na[8], nc[4];
        {
            int s2 = (s + 1 < TT) ? s + 1 : s;
            int t2 = d ? (TT - 1 - s2) : s2;
            const float* gxn = gxd + (size_t)t2 * 96 * BB;
            #pragma unroll
            for (int jj = 0; jj < 8; jj++) na[jj] = ld2(&gxn[(size_t)(j0 + jj) * BB + b0]);
            #pragma unroll
            for (int jj = 0; jj < 4; jj++) nc[jj] = ld2(&gxn[(size_t)(64 + jc0 + jj) * BB + b0]);
        }
        // ---- gate phase ----
        #pragma unroll
        for (int k = 0; k < 32; k++) {
            ull h2 = sH[lb][k];
            const float4* w4 = (const float4*)&sWg[k][j0];
            float4 w0 = w4[0], w1 = w4[1];
            a[0] = fma2(h2, bc2(w0.x), a[0]);
            a[1] = fma2(h2, bc2(w0.y), a[1]);
            a[2] = fma2(h2, bc2(w0.z), a[2]);
            a[3] = fma2(h2, bc2(w0.w), a[3]);
            a[4] = fma2(h2, bc2(w1.x), a[4]);
            a[5] = fma2(h2, bc2(w1.y), a[5]);
            a[6] = fma2(h2, bc2(w1.z), a[6]);
            a[7] = fma2(h2, bc2(w1.w), a[7]);
        }
        if (jg < 4) {
            #pragma unroll
            for (int jj = 0; jj < 8; jj++) {
                int kk = j0 + jj;
                float alo, ahi, hlo, hhi;
                upk2(a[jj], alo, ahi);
                upk2(sH[lb][kk], hlo, hhi);
                sRH[lb][kk] = pk2(sigmoidf_(alo) * hlo, sigmoidf_(ahi) * hhi);
            }
        } else {
            #pragma unroll
            for (int jj = 0; jj < 8; jj++) {
                int kk = j0 + jj - 32;
                float alo, ahi;
                upk2(a[jj], alo, ahi);
                sU[lb][kk] = pk2(sigmoidf_(alo), sigmoidf_(ahi));
            }
        }
        __syncthreads();
        // ---- fused candidate + update ----
        ull c[4];
        #pragma unroll
        for (int jj = 0; jj < 4; jj++) c[jj] = cc[jj];
        #pragma unroll
        for (int k = 0; k < 32; k++) {
            ull rh = sRH[lb][k];
            const float4* w4 = (const float4*)&sWc[k][jc0];
            float4 w = w4[0];
            c[0] = fma2(rh, bc2(w.x), c[0]);
            c[1] = fma2(rh, bc2(w.y), c[1]);
            c[2] = fma2(rh, bc2(w.z), c[2]);
            c[3] = fma2(rh, bc2(w.w), c[3]);
        }
        float f0[4], f1[4];
        #pragma unroll
        for (int jj = 0; jj < 4; jj++) {
            int k = jc0 + jj;
            float clo, chi, ulo, uhi, hlo, hhi;
            upk2(c[jj], clo, chi);
            clo = tanhf_(clo); chi = tanhf_(chi);
            upk2(sU[lb][k], ulo, uhi);
            upk2(sH[lb][k], hlo, hhi);
            float hn0 = ulo * hlo + (1.0f - ulo) * clo;
            float hn1 = uhi * hhi + (1.0f - uhi) * chi;
            sH[lb][k] = pk2(hn0, hn1);
            f0[jj] = hn0; f1[jj] = hn1;
        }
        if (direct) {
            float* ob = y + (size_t)b0 * (TT * 64) + t * 64 + ycol + jc0;
            *(float4*)ob = make_float4(f0[0], f0[1], f0[2], f0[3]);
            *(float4*)(ob + TT * 64) = make_float4(f1[0], f1[1], f1[2], f1[3]);
        } else {
            float* yout = y + (size_t)t * 64 * BB + (size_t)ycol * BB + b0;
            #pragma unroll
            for (int jj = 0; jj < 4; jj++)
                st2(&yout[(size_t)(jc0 + jj) * BB], pk2(f0[jj], f1[jj]));
        }
        // rotate prefetched registers into current
        #pragma unroll
        for (int jj = 0; jj < 8; jj++) a[jj] = na[jj];
        #pragma unroll
        for (int jj = 0; jj < 4; jj++) cc[jj] = nc[jj];
        __syncthreads();
    }
}

// ---------------- launch ----------------
extern "C" void kernel_launch(void* const* d_in, const int* in_sizes, int n_in,
                              void* d_out, int out_size) {
    const int*   tokens_before = (const int*)d_in[0];
    const int*   types_before  = (const int*)d_in[1];
    const void*  mask_before   = d_in[2];
    const int*   tokens_after  = (const int*)d_in[3];
    const int*   types_after   = (const int*)d_in[4];
    const void*  mask_after    = d_in[5];
    const float* token_emb     = (const float*)d_in[6];
    const float* type_emb      = (const float*)d_in[7];
    const float* hole          = (const float*)d_in[8];
    const float* gk_fw0 = (const float*)d_in[9];
    const float* gb_fw0 = (const float*)d_in[10];
    const float* ck_fw0 = (const float*)d_in[11];
    const float* cb_fw0 = (const float*)d_in[12];
    const float* gk_bw0 = (const float*)d_in[13];
    const float* gb_bw0 = (const float*)d_in[14];
    const float* ck_bw0 = (const float*)d_in[15];
    const float* cb_bw0 = (const float*)d_in[16];
    const float* gk_fw1 = (const float*)d_in[17];
    const float* gb_fw1 = (const float*)d_in[18];
    const float* ck_fw1 = (const float*)d_in[19];
    const float* cb_fw1 = (const float*)d_in[20];
    const float* gk_bw1 = (const float*)d_in[21];
    const float* gb_bw1 = (const float*)d_in[22];
    const float* ck_bw1 = (const float*)d_in[23];
    const float* cb_bw1 = (const float*)d_in[24];
    float* out = (float*)d_out;

    float* gx0; cudaGetSymbolAddress((void**)&gx0, g_gx0);
    float* gx1; cudaGetSymbolAddress((void**)&gx1, g_gx1);
    float* y0;  cudaGetSymbolAddress((void**)&y0,  g_y0);

    k_detect<<<1, 256>>>((const unsigned char*)mask_before);
    k_typemax<<<dim3(BB / 32, 20), dim3(8, 32)>>>(types_before, mask_before, types_after, mask_after, type_emb);
    k_tokproj<<<VT + 1, 192>>>(token_emb, hole,
                               gk_fw0, gb_fw0, ck_fw0, cb_fw0,
                               gk_bw0, gb_bw0, ck_bw0, cb_bw0);
    k_x0<<<dim3(BB / 64, TT, 2), dim3(32, 8)>>>(tokens_before, tokens_after,
                                                gk_fw0, ck_fw0, gk_bw0, ck_bw0);
    k_scan<<<dim3(BB / 64, 2), dim3(32, 8)>>>(gx0, y0, gk_fw0, ck_fw0, gk_bw0, ck_bw0, 160, 0);
    k_x1<<<dim3(BB / 128, TT, 2), dim3(32, 8)>>>(gk_fw1, gb_fw1, ck_fw1, cb_fw1,
                                                 gk_bw1, gb_bw1, ck_bw1, cb_bw1);
    k_scan<<<dim3(BB / 64, 2), dim3(32, 8)>>>(gx1, out, gk_fw1, ck_fw1, gk_bw1, ck_bw1, 64, 1);
}

// round 13
// speedup vs baseline: 1.5308x; 1.5308x over previous
#include <cuda_runtime.h>
#include <math.h>

// R13 = R12 resubmitted unchanged: R12's bench showed identical k_x0 code 44% slower
// than R7 at equal regs/smem/grid (and proportionally slower everything else) ->
// DVFS/environment artifact. Clean re-measurement to attribute R11->R12 code changes.

#define BB   8192
#define TT   21
#define NTY  10
#define VT   5000

typedef unsigned long long ull;

// ---------------- device scratch ----------------
__device__ __align__(16) float g_tokproj[2][VT][96];
__device__ __align__(16) float g_holeproj[2][96];
__device__ __align__(16) float g_tmax[21][32][BB];
__device__ __align__(16) float g_gx0[2][21][96][BB];
__device__ __align__(16) float g_y0[21][64][BB];
__device__ __align__(16) float g_gx1[2][21][96][BB];
__device__ int   g_mask_kind;

// ---------------- packed f32x2 helpers ----------------
__device__ __forceinline__ ull pk2(float lo, float hi) {
    ull r; asm("mov.b64 %0, {%1,%2};" : "=l"(r) : "f"(lo), "f"(hi)); return r;
}
__device__ __forceinline__ ull bc2(float v) {
    ull r; asm("mov.b64 %0, {%1,%1};" : "=l"(r) : "f"(v)); return r;
}
__device__ __forceinline__ void upk2(ull v, float& lo, float& hi) {
    asm("mov.b64 {%0,%1}, %2;" : "=f"(lo), "=f"(hi) : "l"(v));
}
__device__ __forceinline__ ull fma2(ull a, ull b, ull c) {
    ull d; asm("fma.rn.f32x2 %0, %1, %2, %3;" : "=l"(d) : "l"(a), "l"(b), "l"(c)); return d;
}
__device__ __forceinline__ ull ld2(const float* p) { return *(const ull*)p; }
__device__ __forceinline__ void st2(float* p, ull v) { *(ull*)p = v; }

__device__ __forceinline__ float sigmoidf_(float x) {
    return __fdividef(1.0f, 1.0f + __expf(-x));
}
__device__ __forceinline__ float tanhf_(float x) {
    x = fminf(fmaxf(x, -15.0f), 15.0f);
    float e = __expf(2.0f * x);
    return __fdividef(e - 1.0f, e + 1.0f);
}

// ---------------- mask dtype detection ----------------
__global__ void k_detect(const unsigned char* __restrict__ m) {
    __shared__ int s_nonbin, s_off;
    if (threadIdx.x == 0) { s_nonbin = 0; s_off = 0; }
    __syncthreads();
    int nonbin = 0, off = 0;
    for (int i = threadIdx.x; i < 4096; i += blockDim.x) {
        unsigned char v = m[i];
        if (v > 1) nonbin = 1;
        if ((i & 3) != 0 && v == 1) off = 1;
    }
    if (nonbin) atomicOr(&s_nonbin, 1);
    if (off)    atomicOr(&s_off, 1);
    __syncthreads();
    if (threadIdx.x == 0)
        g_mask_kind = s_nonbin ? 2 : (s_off ? 1 : 0);
}

// ---------------- vocab / hole projection through layer0 x-rows ----------------
__global__ void k_tokproj(const float* __restrict__ te, const float* __restrict__ hole,
                          const float* __restrict__ gkf, const float* __restrict__ gbf,
                          const float* __restrict__ ckf, const float* __restrict__ cbf,
                          const float* __restrict__ gkb, const float* __restrict__ gbb,
                          const float* __restrict__ ckb, const float* __restrict__ cbb) {
    __shared__ float sx[160];
    int v = blockIdx.x;
    int tid = threadIdx.x;
    bool is_hole = (v == VT);
    int xl = is_hole ? 160 : 128;
    if (is_hole) { if (tid < 160) sx[tid] = hole[tid]; }
    else         { if (tid < 128) sx[tid] = te[v * 128 + tid]; }
    __syncthreads();
    int d = tid / 96, j = tid % 96;
    const float* gk = d ? gkb : gkf;
    const float* ck = d ? ckb : ckf;
    const float* gb = d ? gbb : gbf;
    const float* cb = d ? cbb : cbf;
    float acc = (j < 64) ? gb[j] : cb[j - 64];
    if (j < 64) {
        for (int k = 0; k < xl; k++) acc += sx[k] * gk[k * 64 + j];
    } else {
        int jj = j - 64;
        for (int k = 0; k < xl; k++) acc += sx[k] * ck[k * 32 + jj];
    }
    if (is_hole) g_holeproj[d][j] = acc;
    else         g_tokproj[d][v][j] = acc;
}

// ---------------- masked max over type embeddings ----------------
__global__ void k_typemax(const int* __restrict__ types_b, const void* __restrict__ mask_b,
                          const int* __restrict__ types_a, const void* __restrict__ mask_a,
                          const float* __restrict__ typ_emb) {
    int kg = threadIdx.x, lbv = threadIdx.y;
    int b = blockIdx.x * 32 + lbv;
    int p = blockIdx.y;
    int t = (p < 10) ? p : p + 1;
    const int*  types = (p < 10) ? types_b : types_a;
    const void* maskp = (p < 10) ? mask_b : mask_a;
    int pp = (p < 10) ? p : p - 10;
    int mk = g_mask_kind;
    int base = (b * NTY + pp) * NTY;
    int k0 = kg * 4;
    float m0 = -3.4e38f, m1 = -3.4e38f, m2 = -3.4e38f, m3 = -3.4e38f;
    #pragma unroll
    for (int nt = 0; nt < NTY; nt++) {
        int id = types[base + nt];
        bool valid;
        if (mk == 0)      valid = ((const int*)maskp)[base + nt] != 0;
        else if (mk == 1) valid = ((const unsigned char*)maskp)[base + nt] != 0;
        else              valid = ((const float*)maskp)[base + nt] != 0.0f;
        float pen = valid ? 0.0f : -1000.0f;
        float4 e = *(const float4*)(typ_emb + id * 32 + k0);
        m0 = fmaxf(m0, e.x + pen);
        m1 = fmaxf(m1, e.y + pen);
        m2 = fmaxf(m2, e.z + pen);
        m3 = fmaxf(m3, e.w + pen);
    }
    g_tmax[t][k0 + 0][b] = m0;
    g_tmax[t][k0 + 1][b] = m1;
    g_tmax[t][k0 + 2][b] = m2;
    g_tmax[t][k0 + 3][b] = m3;
}

// ---------------- layer0 x-projection (R7 form: staged gather, direct tmax ld2) ----------------
// grid (BB/64, 21, 2), block (32,8); thread handles b = base+2*lb, base+2*lb+1
__global__ __launch_bounds__(256) void k_x0(const int* __restrict__ tok_b, const int* __restrict__ tok_a,
                     const float* __restrict__ gkf, const float* __restrict__ ckf,
                     const float* __restrict__ gkb, const float* __restrict__ ckb) {
    int d = blockIdx.z, t = blockIdx.y;
    int lb = threadIdx.x, jg = threadIdx.y;
    int b0 = blockIdx.x * 64 + 2 * lb;
    __shared__ __align__(16) float sW[32][96];
    __shared__ float sX[64][97];
    __shared__ int   stok[64];
    const float* gk = d ? gkb : gkf;
    const float* ck = d ? ckb : ckf;
    int tid = jg * 32 + lb;
    for (int i = tid; i < 32 * 96; i += 256) {
        int k = i / 96, j = i % 96;
        sW[k][j] = (j < 64) ? gk[(128 + k) * 64 + j] : ck[(128 + k) * 32 + (j - 64)];
    }
    float* out = &g_gx0[d][t][0][0];
    int j0 = jg * 12;
    if (t == 10) {
        #pragma unroll
        for (int jj = 0; jj < 12; jj++)
            st2(&out[(size_t)(j0 + jj) * BB + b0], bc2(g_holeproj[d][j0 + jj]));
        return;
    }
    int pp = (t < 10) ? t : t - 11;
    if (tid < 64) {
        int bg = blockIdx.x * 64 + tid;
        stok[tid] = (t < 10) ? tok_b[bg * NTY + pp] : tok_a[bg * NTY + pp];
    }
    __syncthreads();
    // cooperative gather of tokproj rows
    for (int i = tid; i < 64 * 24; i += 256) {
        int row = i / 24, q = i - row * 24;
        float4 v = ((const float4*)&g_tokproj[d][stok[row]][0])[q];
        sX[row][q * 4 + 0] = v.x;
        sX[row][q * 4 + 1] = v.y;
        sX[row][q * 4 + 2] = v.z;
        sX[row][q * 4 + 3] = v.w;
    }
    __syncthreads();
    ull acc[12];
    #pragma unroll
    for (int jj = 0; jj < 12; jj++)
        acc[jj] = pk2(sX[2 * lb][j0 + jj], sX[2 * lb + 1][j0 + jj]);
    const float* tm = &g_tmax[t][0][0];
    #pragma unroll
    for (int k = 0; k < 32; k++) {
        ull tv = ld2(&tm[(size_t)k * BB + b0]);
        const float4* w4 = (const float4*)&sW[k][j0];
        float4 w0 = w4[0], w1 = w4[1], w2 = w4[2];
        acc[0]  = fma2(tv, bc2(w0.x), acc[0]);
        acc[1]  = fma2(tv, bc2(w0.y), acc[1]);
        acc[2]  = fma2(tv, bc2(w0.z), acc[2]);
        acc[3]  = fma2(tv, bc2(w0.w), acc[3]);
        acc[4]  = fma2(tv, bc2(w1.x), acc[4]);
        acc[5]  = fma2(tv, bc2(w1.y), acc[5]);
        acc[6]  = fma2(tv, bc2(w1.z), acc[6]);
        acc[7]  = fma2(tv, bc2(w1.w), acc[7]);
        acc[8]  = fma2(tv, bc2(w2.x), acc[8]);
        acc[9]  = fma2(tv, bc2(w2.y), acc[9]);
        acc[10] = fma2(tv, bc2(w2.z), acc[10]);
        acc[11] = fma2(tv, bc2(w2.w), acc[11]);
    }
    #pragma unroll
    for (int jj = 0; jj < 12; jj++)
        st2(&out[(size_t)(j0 + jj) * BB + b0], acc[jj]);
}

// ---------------- layer1 x-projection: 4 batch/thread, staged y, f32x2 ----------------
// grid (BB/128, 21, 2), block (32,8); thread handles b = base+4*lb .. +3
__global__ __launch_bounds__(256) void k_x1(const float* __restrict__ gkf, const float* __restrict__ gbf,
                     const float* __restrict__ ckf, const float* __restrict__ cbf,
                     const float* __restrict__ gkb, const float* __restrict__ gbb,
                     const float* __restrict__ ckb, const float* __restrict__ cbb) {
    int d = blockIdx.z, t = blockIdx.y;
    int lb = threadIdx.x, jg = threadIdx.y;
    int bb = blockIdx.x * 128;
    __shared__ __align__(16) float sW[64][96];
    __shared__ __align__(16) float sY[32][128];
    const float* gk = d ? gkb : gkf;
    const float* ck = d ? ckb : ckf;
    const float* gb = d ? gbb : gbf;
    const float* cb = d ? cbb : cbf;
    int tid = jg * 32 + lb;
    for (int i = tid; i < 64 * 96; i += 256) {
        int k = i / 96, j = i % 96;
        sW[k][j] = (j < 64) ? gk[k * 64 + j] : ck[k * 32 + (j - 64)];
    }
    int j0 = jg * 12;
    ull acc0[12], acc1[12];
    #pragma unroll
    for (int jj = 0; jj < 12; jj++) {
        int j = j0 + jj;
        ull bv = bc2((j < 64) ? gb[j] : cb[j - 64]);
        acc0[jj] = bv; acc1[jj] = bv;
    }
    const float* y = &g_y0[t][0][0] + bb;
    #pragma unroll
    for (int half = 0; half < 2; half++) {
        __syncthreads();
        // stage 32 k-rows x 128 b
        for (int i = tid; i < 1024; i += 256) {
            int k = i >> 5, c = i & 31;
            float4 v = *(const float4*)(y + (size_t)(half * 32 + k) * BB + c * 4);
            *(float4*)&sY[k][c * 4] = v;
        }
        __syncthreads();
        #pragma unroll 8
        for (int k = 0; k < 32; k++) {
            const ull* yp = (const ull*)&sY[k][4 * lb];
            ull y0v = yp[0], y1v = yp[1];
            const float4* w4 = (const float4*)&sW[half * 32 + k][j0];
            float4 w0 = w4[0], w1 = w4[1], w2 = w4[2];
            ull c0, c1, c2;
            c0 = bc2(w0.x); acc0[0]  = fma2(y0v, c0, acc0[0]);  acc1[0]  = fma2(y1v, c0, acc1[0]);
            c1 = bc2(w0.y); acc0[1]  = fma2(y0v, c1, acc0[1]);  acc1[1]  = fma2(y1v, c1, acc1[1]);
            c2 = bc2(w0.z); acc0[2]  = fma2(y0v, c2, acc0[2]);  acc1[2]  = fma2(y1v, c2, acc1[2]);
            c0 = bc2(w0.w); acc0[3]  = fma2(y0v, c0, acc0[3]);  acc1[3]  = fma2(y1v, c0, acc1[3]);
            c1 = bc2(w1.x); acc0[4]  = fma2(y0v, c1, acc0[4]);  acc1[4]  = fma2(y1v, c1, acc1[4]);
            c2 = bc2(w1.y); acc0[5]  = fma2(y0v, c2, acc0[5]);  acc1[5]  = fma2(y1v, c2, acc1[5]);
            c0 = bc2(w1.z); acc0[6]  = fma2(y0v, c0, acc0[6]);  acc1[6]  = fma2(y1v, c0, acc1[6]);
            c1 = bc2(w1.w); acc0[7]  = fma2(y0v, c1, acc0[7]);  acc1[7]  = fma2(y1v, c1, acc1[7]);
            c2 = bc2(w2.x); acc0[8]  = fma2(y0v, c2, acc0[8]);  acc1[8]  = fma2(y1v, c2, acc1[8]);
            c0 = bc2(w2.y); acc0[9]  = fma2(y0v, c0, acc0[9]);  acc1[9]  = fma2(y1v, c0, acc1[9]);
            c1 = bc2(w2.z); acc0[10] = fma2(y0v, c1, acc0[10]); acc1[10] = fma2(y1v, c1, acc1[10]);
            c2 = bc2(w2.w); acc0[11] = fma2(y0v, c2, acc0[11]); acc1[11] = fma2(y1v, c2, acc1[11]);
        }
    }
    float* out = &g_gx1[d][t][0][0] + bb + 4 * lb;
    #pragma unroll
    for (int jj = 0; jj < 12; jj++) {
        ull* o = (ull*)&out[(size_t)(j0 + jj) * BB];
        o[0] = acc0[jj];
        o[1] = acc1[jj];
    }
}

// ---------------- recurrent scan: prefetched gx, adjacent-pair b, optional direct output ----------------
// grid (BB/64, 2), block (32,8)
__global__ __launch_bounds__(256) void k_scan(const float* __restrict__ gx, float* __restrict__ y,
                       const float* __restrict__ gkf, const float* __restrict__ ckf,
                       const float* __restrict__ gkb, const float* __restrict__ ckb,
                       int hoff, int direct) {
    int d = blockIdx.y;
    int lb = threadIdx.x, jg = threadIdx.y;
    int b0 = blockIdx.x * 64 + 2 * lb;
    const float* gk = d ? gkb : gkf;
    const float* ck = d ? ckb : ckf;
    __shared__ __align__(16) float sWg[32][64];
    __shared__ __align__(16) float sWc[32][32];
    __shared__ ull sH[32][33];
    __shared__ ull sRH[32][33];
    __shared__ ull sU[32][33];
    int tid = jg * 32 + lb;
    for (int i = tid; i < 32 * 64; i += 256) { int k = i / 64, j = i % 64; sWg[k][j] = gk[(hoff + k) * 64 + j]; }
    for (int i = tid; i < 32 * 32; i += 256) { int k = i / 32, j = i % 32; sWc[k][j] = ck[(hoff + k) * 32 + j]; }
    for (int i = tid; i < 32 * 32; i += 256) { sH[i / 32][i % 32] = 0ULL; }
    __syncthreads();
    const float* gxd = gx + (size_t)d * TT * 96 * BB;
    int ycol = d ? 32 : 0;
    int j0 = jg * 8;
    int jc0 = jg * 4;
    // software pipeline: preload step 0's x-projections
    ull a[8], cc[4];
    {
        const float* gxt = gxd + (size_t)(d ? TT - 1 : 0) * 96 * BB;
        #pragma unroll
        for (int jj = 0; jj < 8; jj++) a[jj] = ld2(&gxt[(size_t)(j0 + jj) * BB + b0]);
        #pragma unroll
        for (int jj = 0; jj < 4; jj++) cc[jj] = ld2(&gxt[(size_t)(64 + jc0 + jj) * BB + b0]);
    }
    for (int s = 0; s < TT; s++) {
        int t = d ? (TT - 1 - s) : s;
        // ---- prefetch next step's gx into registers (independent of recurrence) ----
        ull na[8], nc[4];
        {
            int s2 = (s + 1 < TT) ? s + 1 : s;
            int t2 = d ? (TT - 1 - s2) : s2;
            const float* gxn = gxd + (size_t)t2 * 96 * BB;
            #pragma unroll
            for (int jj = 0; jj < 8; jj++) na[jj] = ld2(&gxn[(size_t)(j0 + jj) * BB + b0]);
            #pragma unroll
            for (int jj = 0; jj < 4; jj++) nc[jj] = ld2(&gxn[(size_t)(64 + jc0 + jj) * BB + b0]);
        }
        // ---- gate phase ----
        #pragma unroll
        for (int k = 0; k < 32; k++) {
            ull h2 = sH[lb][k];
            const float4* w4 = (const float4*)&sWg[k][j0];
            float4 w0 = w4[0], w1 = w4[1];
            a[0] = fma2(h2, bc2(w0.x), a[0]);
            a[1] = fma2(h2, bc2(w0.y), a[1]);
            a[2] = fma2(h2, bc2(w0.z), a[2]);
            a[3] = fma2(h2, bc2(w0.w), a[3]);
            a[4] = fma2(h2, bc2(w1.x), a[4]);
            a[5] = fma2(h2, bc2(w1.y), a[5]);
            a[6] = fma2(h2, bc2(w1.z), a[6]);
            a[7] = fma2(h2, bc2(w1.w), a[7]);
        }
        if (jg < 4) {
            #pragma unroll
            for (int jj = 0; jj < 8; jj++) {
                int kk = j0 + jj;
                float alo, ahi, hlo, hhi;
                upk2(a[jj], alo, ahi);
                upk2(sH[lb][kk], hlo, hhi);
                sRH[lb][kk] = pk2(sigmoidf_(alo) * hlo, sigmoidf_(ahi) * hhi);
            }
        } else {
            #pragma unroll
            for (int jj = 0; jj < 8; jj++) {
                int kk = j0 + jj - 32;
                float alo, ahi;
                upk2(a[jj], alo, ahi);
                sU[lb][kk] = pk2(sigmoidf_(alo), sigmoidf_(ahi));
            }
        }
        __syncthreads();
        // ---- fused candidate + update ----
        ull c[4];
        #pragma unroll
        for (int jj = 0; jj < 4; jj++) c[jj] = cc[jj];
        #pragma unroll
        for (int k = 0; k < 32; k++) {
            ull rh = sRH[lb][k];
            const float4* w4 = (const float4*)&sWc[k][jc0];
            float4 w = w4[0];
            c[0] = fma2(rh, bc2(w.x), c[0]);
            c[1] = fma2(rh, bc2(w.y), c[1]);
            c[2] = fma2(rh, bc2(w.z), c[2]);
            c[3] = fma2(rh, bc2(w.w), c[3]);
        }
        float f0[4], f1[4];
        #pragma unroll
        for (int jj = 0; jj < 4; jj++) {
            int k = jc0 + jj;
            float clo, chi, ulo, uhi, hlo, hhi;
            upk2(c[jj], clo, chi);
            clo = tanhf_(clo); chi = tanhf_(chi);
            upk2(sU[lb][k], ulo, uhi);
            upk2(sH[lb][k], hlo, hhi);
            float hn0 = ulo * hlo + (1.0f - ulo) * clo;
            float hn1 = uhi * hhi + (1.0f - uhi) * chi;
            sH[lb][k] = pk2(hn0, hn1);
            f0[jj] = hn0; f1[jj] = hn1;
        }
        if (direct) {
            float* ob = y + (size_t)b0 * (TT * 64) + t * 64 + ycol + jc0;
            *(float4*)ob = make_float4(f0[0], f0[1], f0[2], f0[3]);
            *(float4*)(ob + TT * 64) = make_float4(f1[0], f1[1], f1[2], f1[3]);
        } else {
            float* yout = y + (size_t)t * 64 * BB + (size_t)ycol * BB + b0;
            #pragma unroll
            for (int jj = 0; jj < 4; jj++)
                st2(&yout[(size_t)(jc0 + jj) * BB], pk2(f0[jj], f1[jj]));
        }
        // rotate prefetched registers into current
        #pragma unroll
        for (int jj = 0; jj < 8; jj++) a[jj] = na[jj];
        #pragma unroll
        for (int jj = 0; jj < 4; jj++) cc[jj] = nc[jj];
        __syncthreads();
    }
}

// ---------------- launch ----------------
extern "C" void kernel_launch(void* const* d_in, const int* in_sizes, int n_in,
                              void* d_out, int out_size) {
    const int*   tokens_before = (const int*)d_in[0];
    const int*   types_before  = (const int*)d_in[1];
    const void*  mask_before   = d_in[2];
    const int*   tokens_after  = (const int*)d_in[3];
    const int*   types_after   = (const int*)d_in[4];
    const void*  mask_after    = d_in[5];
    const float* token_emb     = (const float*)d_in[6];
    const float* type_emb      = (const float*)d_in[7];
    const float* hole          = (const float*)d_in[8];
    const float* gk_fw0 = (const float*)d_in[9];
    const float* gb_fw0 = (const float*)d_in[10];
    const float* ck_fw0 = (const float*)d_in[11];
    const float* cb_fw0 = (const float*)d_in[12];
    const float* gk_bw0 = (const float*)d_in[13];
    const float* gb_bw0 = (const float*)d_in[14];
    const float* ck_bw0 = (const float*)d_in[15];
    const float* cb_bw0 = (const float*)d_in[16];
    const float* gk_fw1 = (const float*)d_in[17];
    const float* gb_fw1 = (const float*)d_in[18];
    const float* ck_fw1 = (const float*)d_in[19];
    const float* cb_fw1 = (const float*)d_in[20];
    const float* gk_bw1 = (const float*)d_in[21];
    const float* gb_bw1 = (const float*)d_in[22];
    const float* ck_bw1 = (const float*)d_in[23];
    const float* cb_bw1 = (const float*)d_in[24];
    float* out = (float*)d_out;

    float* gx0; cudaGetSymbolAddress((void**)&gx0, g_gx0);
    float* gx1; cudaGetSymbolAddress((void**)&gx1, g_gx1);
    float* y0;  cudaGetSymbolAddress((void**)&y0,  g_y0);

    k_detect<<<1, 256>>>((const unsigned char*)mask_before);
    k_typemax<<<dim3(BB / 32, 20), dim3(8, 32)>>>(types_before, mask_before, types_after, mask_after, type_emb);
    k_tokproj<<<VT + 1, 192>>>(token_emb, hole,
                               gk_fw0, gb_fw0, ck_fw0, cb_fw0,
                               gk_bw0, gb_bw0, ck_bw0, cb_bw0);
    k_x0<<<dim3(BB / 64, TT, 2), dim3(32, 8)>>>(tokens_before, tokens_after,
                                                gk_fw0, ck_fw0, gk_bw0, ck_bw0);
    k_scan<<<dim3(BB / 64, 2), dim3(32, 8)>>>(gx0, y0, gk_fw0, ck_fw0, gk_bw0, ck_bw0, 160, 0);
    k_x1<<<dim3(BB / 128, TT, 2), dim3(32, 8)>>>(gk_fw1, gb_fw1, ck_fw1, cb_fw1,
                                                 gk_bw1, gb_bw1, ck_bw1, cb_bw1);
    k_scan<<<dim3(BB / 64, 2), dim3(32, 8)>>>(gx1, out, gk_fw1, ck_fw1, gk_bw1, ck_bw1, 64, 1);
}

// round 15
// speedup vs baseline: 1.5538x; 1.0150x over previous
#include <cuda_runtime.h>
#include <math.h>

#define BB   8192
#define TT   21
#define NTY  10
#define VT   5000

typedef unsigned long long ull;

// ---------------- device scratch ----------------
__device__ __align__(16) float g_tokproj[2][VT][96];
__device__ __align__(16) float g_holeproj[2][96];
__device__ __align__(16) float g_tmax[21][32][BB];
__device__ __align__(16) float g_gx0[2][21][96][BB];
__device__ __align__(16) float g_y0[21][64][BB];
__device__ int   g_mask_kind;

// ---------------- packed f32x2 helpers ----------------
__device__ __forceinline__ ull pk2(float lo, float hi) {
    ull r; asm("mov.b64 %0, {%1,%2};" : "=l"(r) : "f"(lo), "f"(hi)); return r;
}
__device__ __forceinline__ ull bc2(float v) {
    ull r; asm("mov.b64 %0, {%1,%1};" : "=l"(r) : "f"(v)); return r;
}
__device__ __forceinline__ void upk2(ull v, float& lo, float& hi) {
    asm("mov.b64 {%0,%1}, %2;" : "=f"(lo), "=f"(hi) : "l"(v));
}
__device__ __forceinline__ ull fma2(ull a, ull b, ull c) {
    ull d; asm("fma.rn.f32x2 %0, %1, %2, %3;" : "=l"(d) : "l"(a), "l"(b), "l"(c)); return d;
}
__device__ __forceinline__ ull ld2(const float* p) { return *(const ull*)p; }
__device__ __forceinline__ void st2(float* p, ull v) { *(ull*)p = v; }

__device__ __forceinline__ float sigmoidf_(float x) {
    return __fdividef(1.0f, 1.0f + __expf(-x));
}
__device__ __forceinline__ float tanhf_(float x) {
    x = fminf(fmaxf(x, -15.0f), 15.0f);
    float e = __expf(2.0f * x);
    return __fdividef(e - 1.0f, e + 1.0f);
}

// ---------------- mask dtype detection ----------------
__global__ void k_detect(const unsigned char* __restrict__ m) {
    __shared__ int s_nonbin, s_off;
    if (threadIdx.x == 0) { s_nonbin = 0; s_off = 0; }
    __syncthreads();
    int nonbin = 0, off = 0;
    for (int i = threadIdx.x; i < 4096; i += blockDim.x) {
        unsigned char v = m[i];
        if (v > 1) nonbin = 1;
        if ((i & 3) != 0 && v == 1) off = 1;
    }
    if (nonbin) atomicOr(&s_nonbin, 1);
    if (off)    atomicOr(&s_off, 1);
    __syncthreads();
    if (threadIdx.x == 0)
        g_mask_kind = s_nonbin ? 2 : (s_off ? 1 : 0);
}

// ---------------- vocab / hole projection through layer0 x-rows ----------------
__global__ void k_tokproj(const float* __restrict__ te, const float* __restrict__ hole,
                          const float* __restrict__ gkf, const float* __restrict__ gbf,
                          const float* __restrict__ ckf, const float* __restrict__ cbf,
                          const float* __restrict__ gkb, const float* __restrict__ gbb,
                          const float* __restrict__ ckb, const float* __restrict__ cbb) {
    __shared__ float sx[160];
    int v = blockIdx.x;
    int tid = threadIdx.x;
    bool is_hole = (v == VT);
    int xl = is_hole ? 160 : 128;
    if (is_hole) { if (tid < 160) sx[tid] = hole[tid]; }
    else         { if (tid < 128) sx[tid] = te[v * 128 + tid]; }
    __syncthreads();
    int d = tid / 96, j = tid % 96;
    const float* gk = d ? gkb : gkf;
    const float* ck = d ? ckb : ckf;
    const float* gb = d ? gbb : gbf;
    const float* cb = d ? cbb : cbf;
    float acc = (j < 64) ? gb[j] : cb[j - 64];
    if (j < 64) {
        for (int k = 0; k < xl; k++) acc += sx[k] * gk[k * 64 + j];
    } else {
        int jj = j - 64;
        for (int k = 0; k < xl; k++) acc += sx[k] * ck[k * 32 + jj];
    }
    if (is_hole) g_holeproj[d][j] = acc;
    else         g_tokproj[d][v][j] = acc;
}

// ---------------- masked max over type embeddings ----------------
__global__ void k_typemax(const int* __restrict__ types_b, const void* __restrict__ mask_b,
                          const int* __restrict__ types_a, const void* __restrict__ mask_a,
                          const float* __restrict__ typ_emb) {
    int kg = threadIdx.x, lbv = threadIdx.y;
    int b = blockIdx.x * 32 + lbv;
    int p = blockIdx.y;
    int t = (p < 10) ? p : p + 1;
    const int*  types = (p < 10) ? types_b : types_a;
    const void* maskp = (p < 10) ? mask_b : mask_a;
    int pp = (p < 10) ? p : p - 10;
    int mk = g_mask_kind;
    int base = (b * NTY + pp) * NTY;
    int k0 = kg * 4;
    float m0 = -3.4e38f, m1 = -3.4e38f, m2 = -3.4e38f, m3 = -3.4e38f;
    #pragma unroll
    for (int nt = 0; nt < NTY; nt++) {
        int id = types[base + nt];
        bool valid;
        if (mk == 0)      valid = ((const int*)maskp)[base + nt] != 0;
        else if (mk == 1) valid = ((const unsigned char*)maskp)[base + nt] != 0;
        else              valid = ((const float*)maskp)[base + nt] != 0.0f;
        float pen = valid ? 0.0f : -1000.0f;
        float4 e = *(const float4*)(typ_emb + id * 32 + k0);
        m0 = fmaxf(m0, e.x + pen);
        m1 = fmaxf(m1, e.y + pen);
        m2 = fmaxf(m2, e.z + pen);
        m3 = fmaxf(m3, e.w + pen);
    }
    g_tmax[t][k0 + 0][b] = m0;
    g_tmax[t][k0 + 1][b] = m1;
    g_tmax[t][k0 + 2][b] = m2;
    g_tmax[t][k0 + 3][b] = m3;
}

// ---------------- layer0 x-projection (R7 form) ----------------
// grid (BB/64, 21, 2), block (32,8)
__global__ __launch_bounds__(256) void k_x0(const int* __restrict__ tok_b, const int* __restrict__ tok_a,
                     const float* __restrict__ gkf, const float* __restrict__ ckf,
                     const float* __restrict__ gkb, const float* __restrict__ ckb) {
    int d = blockIdx.z, t = blockIdx.y;
    int lb = threadIdx.x, jg = threadIdx.y;
    int b0 = blockIdx.x * 64 + 2 * lb;
    __shared__ __align__(16) float sW[32][96];
    __shared__ float sX[64][97];
    __shared__ int   stok[64];
    const float* gk = d ? gkb : gkf;
    const float* ck = d ? ckb : ckf;
    int tid = jg * 32 + lb;
    for (int i = tid; i < 32 * 96; i += 256) {
        int k = i / 96, j = i % 96;
        sW[k][j] = (j < 64) ? gk[(128 + k) * 64 + j] : ck[(128 + k) * 32 + (j - 64)];
    }
    float* out = &g_gx0[d][t][0][0];
    int j0 = jg * 12;
    if (t == 10) {
        #pragma unroll
        for (int jj = 0; jj < 12; jj++)
            st2(&out[(size_t)(j0 + jj) * BB + b0], bc2(g_holeproj[d][j0 + jj]));
        return;
    }
    int pp = (t < 10) ? t : t - 11;
    if (tid < 64) {
        int bg = blockIdx.x * 64 + tid;
        stok[tid] = (t < 10) ? tok_b[bg * NTY + pp] : tok_a[bg * NTY + pp];
    }
    __syncthreads();
    for (int i = tid; i < 64 * 24; i += 256) {
        int row = i / 24, q = i - row * 24;
        float4 v = ((const float4*)&g_tokproj[d][stok[row]][0])[q];
        sX[row][q * 4 + 0] = v.x;
        sX[row][q * 4 + 1] = v.y;
        sX[row][q * 4 + 2] = v.z;
        sX[row][q * 4 + 3] = v.w;
    }
    __syncthreads();
    ull acc[12];
    #pragma unroll
    for (int jj = 0; jj < 12; jj++)
        acc[jj] = pk2(sX[2 * lb][j0 + jj], sX[2 * lb + 1][j0 + jj]);
    const float* tm = &g_tmax[t][0][0];
    #pragma unroll
    for (int k = 0; k < 32; k++) {
        ull tv = ld2(&tm[(size_t)k * BB + b0]);
        const float4* w4 = (const float4*)&sW[k][j0];
        float4 w0 = w4[0], w1 = w4[1], w2 = w4[2];
        acc[0]  = fma2(tv, bc2(w0.x), acc[0]);
        acc[1]  = fma2(tv, bc2(w0.y), acc[1]);
        acc[2]  = fma2(tv, bc2(w0.z), acc[2]);
        acc[3]  = fma2(tv, bc2(w0.w), acc[3]);
        acc[4]  = fma2(tv, bc2(w1.x), acc[4]);
        acc[5]  = fma2(tv, bc2(w1.y), acc[5]);
        acc[6]  = fma2(tv, bc2(w1.z), acc[6]);
        acc[7]  = fma2(tv, bc2(w1.w), acc[7]);
        acc[8]  = fma2(tv, bc2(w2.x), acc[8]);
        acc[9]  = fma2(tv, bc2(w2.y), acc[9]);
        acc[10] = fma2(tv, bc2(w2.z), acc[10]);
        acc[11] = fma2(tv, bc2(w2.w), acc[11]);
    }
    #pragma unroll
    for (int jj = 0; jj < 12; jj++)
        st2(&out[(size_t)(j0 + jj) * BB + b0], acc[jj]);
}

// ---------------- layer0 recurrent scan: prefetched gx (R11 form, direct=0 path) ----------------
// grid (BB/64, 2), block (32,8)
__global__ __launch_bounds__(256) void k_scan(const float* __restrict__ gx, float* __restrict__ y,
                       const float* __restrict__ gkf, const float* __restrict__ ckf,
                       const float* __restrict__ gkb, const float* __restrict__ ckb,
                       int hoff) {
    int d = blockIdx.y;
    int lb = threadIdx.x, jg = threadIdx.y;
    int b0 = blockIdx.x * 64 + 2 * lb;
    const float* gk = d ? gkb : gkf;
    const float* ck = d ? ckb : ckf;
    __shared__ __align__(16) float sWg[32][64];
    __shared__ __align__(16) float sWc[32][32];
    __shared__ ull sH[32][33];
    __shared__ ull sRH[32][33];
    __shared__ ull sU[32][33];
    int tid = jg * 32 + lb;
    for (int i = tid; i < 32 * 64; i += 256) { int k = i / 64, j = i % 64; sWg[k][j] = gk[(hoff + k) * 64 + j]; }
    for (int i = tid; i < 32 * 32; i += 256) { int k = i / 32, j = i % 32; sWc[k][j] = ck[(hoff + k) * 32 + j]; }
    for (int i = tid; i < 32 * 32; i += 256) { sH[i / 32][i % 32] = 0ULL; }
    __syncthreads();
    const float* gxd = gx + (size_t)d * TT * 96 * BB;
    int ycol = d ? 32 : 0;
    int j0 = jg * 8;
    int jc0 = jg * 4;
    ull a[8], cc[4];
    {
        const float* gxt = gxd + (size_t)(d ? TT - 1 : 0) * 96 * BB;
        #pragma unroll
        for (int jj = 0; jj < 8; jj++) a[jj] = ld2(&gxt[(size_t)(j0 + jj) * BB + b0]);
        #pragma unroll
        for (int jj = 0; jj < 4; jj++) cc[jj] = ld2(&gxt[(size_t)(64 + jc0 + jj) * BB + b0]);
    }
    for (int s = 0; s < TT; s++) {
        int t = d ? (TT - 1 - s) : s;
        ull na[8], nc[4];
        {
            int s2 = (s + 1 < TT) ? s + 1 : s;
            int t2 = d ? (TT - 1 - s2) : s2;
            const float* gxn = gxd + (size_t)t2 * 96 * BB;
            #pragma unroll
            for (int jj = 0; jj < 8; jj++) na[jj] = ld2(&gxn[(size_t)(j0 + jj) * BB + b0]);
            #pragma unroll
            for (int jj = 0; jj < 4; jj++) nc[jj] = ld2(&gxn[(size_t)(64 + jc0 + jj) * BB + b0]);
        }
        #pragma unroll
        for (int k = 0; k < 32; k++) {
            ull h2 = sH[lb][k];
            const float4* w4 = (const float4*)&sWg[k][j0];
            float4 w0 = w4[0], w1 = w4[1];
            a[0] = fma2(h2, bc2(w0.x), a[0]);
            a[1] = fma2(h2, bc2(w0.y), a[1]);
            a[2] = fma2(h2, bc2(w0.z), a[2]);
            a[3] = fma2(h2, bc2(w0.w), a[3]);
            a[4] = fma2(h2, bc2(w1.x), a[4]);
            a[5] = fma2(h2, bc2(w1.y), a[5]);
            a[6] = fma2(h2, bc2(w1.z), a[6]);
            a[7] = fma2(h2, bc2(w1.w), a[7]);
        }
        if (jg < 4) {
            #pragma unroll
            for (int jj = 0; jj < 8; jj++) {
                int kk = j0 + jj;
                float alo, ahi, hlo, hhi;
                upk2(a[jj], alo, ahi);
                upk2(sH[lb][kk], hlo, hhi);
                sRH[lb][kk] = pk2(sigmoidf_(alo) * hlo, sigmoidf_(ahi) * hhi);
            }
        } else {
            #pragma unroll
            for (int jj = 0; jj < 8; jj++) {
                int kk = j0 + jj - 32;
                float alo, ahi;
                upk2(a[jj], alo, ahi);
                sU[lb][kk] = pk2(sigmoidf_(alo), sigmoidf_(ahi));
            }
        }
        __syncthreads();
        ull c[4];
        #pragma unroll
        for (int jj = 0; jj < 4; jj++) c[jj] = cc[jj];
        #pragma unroll
        for (int k = 0; k < 32; k++) {
            ull rh = sRH[lb][k];
            const float4* w4 = (const float4*)&sWc[k][jc0];
            float4 w = w4[0];
            c[0] = fma2(rh, bc2(w.x), c[0]);
            c[1] = fma2(rh, bc2(w.y), c[1]);
            c[2] = fma2(rh, bc2(w.z), c[2]);
            c[3] = fma2(rh, bc2(w.w), c[3]);
        }
        float* yout = y + (size_t)t * 64 * BB + (size_t)ycol * BB + b0;
        #pragma unroll
        for (int jj = 0; jj < 4; jj++) {
            int k = jc0 + jj;
            float clo, chi, ulo, uhi, hlo, hhi;
            upk2(c[jj], clo, chi);
            clo = tanhf_(clo); chi = tanhf_(chi);
            upk2(sU[lb][k], ulo, uhi);
            upk2(sH[lb][k], hlo, hhi);
            float hn0 = ulo * hlo + (1.0f - ulo) * clo;
            float hn1 = uhi * hhi + (1.0f - uhi) * chi;
            ull hn = pk2(hn0, hn1);
            sH[lb][k] = hn;
            st2(&yout[(size_t)k * BB], hn);
        }
        #pragma unroll
        for (int jj = 0; jj < 8; jj++) a[jj] = na[jj];
        #pragma unroll
        for (int jj = 0; jj < 4; jj++) cc[jj] = nc[jj];
        __syncthreads();
    }
}

// ---------------- layer1 FUSED scan: computes x-projection from y0 on the fly ----------------
// grid (BB/64, 2), block (32,8), dynamic smem. Writes out[b][t][i] directly.
#define SM1F_BYTES 94976
__global__ __launch_bounds__(256) void k_scan1f(const float* __restrict__ y0g, float* __restrict__ out,
                        const float* __restrict__ gkf, const float* __restrict__ gbf,
                        const float* __restrict__ ckf, const float* __restrict__ cbf,
                        const float* __restrict__ gkb, const float* __restrict__ gbb,
                        const float* __restrict__ ckb, const float* __restrict__ cbb) {
    extern __shared__ __align__(16) char dsm[];
    float* sW1 = (float*)dsm;                 // [64][96] x-part weights
    float* sWg = sW1 + 64 * 96;               // [32][64] h-part gate
    float* sWc = sWg + 32 * 64;               // [32][32] h-part cand
    ull*   sH  = (ull*)(sWc + 32 * 32);       // [32][33]
    ull*   sRH = sH + 32 * 33;
    ull*   sU  = sRH + 32 * 33;
    float* sY  = (float*)(sU + 32 * 33);      // [2][64][64]

    int d = blockIdx.y;
    int lb = threadIdx.x, jg = threadIdx.y;
    int bb = blockIdx.x * 64;
    int b0 = bb + 2 * lb;
    const float* gk = d ? gkb : gkf;
    const float* ck = d ? ckb : ckf;
    const float* gb = d ? gbb : gbf;
    const float* cb = d ? cbb : cbf;
    int tid = jg * 32 + lb;
    // load weights
    for (int i = tid; i < 64 * 96; i += 256) {
        int k = i / 96, j = i % 96;
        sW1[i] = (j < 64) ? gk[k * 64 + j] : ck[k * 32 + (j - 64)];
    }
    for (int i = tid; i < 32 * 64; i += 256) { int k = i / 64, j = i % 64; sWg[i] = gk[(64 + k) * 64 + j]; }
    for (int i = tid; i < 32 * 32; i += 256) { int k = i / 32, j = i % 32; sWc[i] = ck[(64 + k) * 32 + j]; }
    for (int i = tid; i < 32 * 32; i += 256) { sH[(i / 32) * 33 + (i % 32)] = 0ULL; }
    int j0 = jg * 8;
    int jc0 = jg * 4;
    // bias registers
    ull bg[8], bcn[4];
    #pragma unroll
    for (int jj = 0; jj < 8; jj++) bg[jj] = bc2(gb[j0 + jj]);
    #pragma unroll
    for (int jj = 0; jj < 4; jj++) bcn[jj] = bc2(cb[jc0 + jj]);
    // prologue: stage tile for step 0 into buffer 0
    {
        int t0 = d ? TT - 1 : 0;
        const float* src = y0g + (size_t)t0 * 64 * BB + bb;
        for (int i = tid; i < 64 * 64; i += 256) {
            int k = i >> 6, c = i & 63;
            sY[k * 64 + c] = src[(size_t)k * BB + c];
        }
    }
    __syncthreads();
    int ycol = d ? 32 : 0;
    int prow = tid >> 2;              // prefetch row (k)
    int pc0  = (tid & 3) * 16;        // prefetch col base
    for (int s = 0; s < TT; s++) {
        int t = d ? (TT - 1 - s) : s;
        int buf = s & 1;
        const float* sYb = sY + buf * 4096;
        // prefetch next step's tile into registers
        float4 p0, p1, p2, p3;
        {
            int s2 = (s + 1 < TT) ? s + 1 : s;
            int t2 = d ? (TT - 1 - s2) : s2;
            const float4* src = (const float4*)(y0g + (size_t)(t2 * 64 + prow) * BB + bb + pc0);
            p0 = src[0]; p1 = src[1]; p2 = src[2]; p3 = src[3];
        }
        // ---- phase 1: x-projection (64 k) + recurrent gate (32 k) ----
        ull a[8], c4[4];
        #pragma unroll
        for (int jj = 0; jj < 8; jj++) a[jj] = bg[jj];
        #pragma unroll
        for (int jj = 0; jj < 4; jj++) c4[jj] = bcn[jj];
        #pragma unroll 8
        for (int k = 0; k < 64; k++) {
            ull yv = *(const ull*)&sYb[k * 64 + 2 * lb];
            const float* wr = &sW1[k * 96];
            float4 w0 = *(const float4*)&wr[j0];
            float4 w1 = *(const float4*)&wr[j0 + 4];
            float4 wc = *(const float4*)&wr[64 + jc0];
            a[0] = fma2(yv, bc2(w0.x), a[0]);
            a[1] = fma2(yv, bc2(w0.y), a[1]);
            a[2] = fma2(yv, bc2(w0.z), a[2]);
            a[3] = fma2(yv, bc2(w0.w), a[3]);
            a[4] = fma2(yv, bc2(w1.x), a[4]);
            a[5] = fma2(yv, bc2(w1.y), a[5]);
            a[6] = fma2(yv, bc2(w1.z), a[6]);
            a[7] = fma2(yv, bc2(w1.w), a[7]);
            c4[0] = fma2(yv, bc2(wc.x), c4[0]);
            c4[1] = fma2(yv, bc2(wc.y), c4[1]);
            c4[2] = fma2(yv, bc2(wc.z), c4[2]);
            c4[3] = fma2(yv, bc2(wc.w), c4[3]);
        }
        #pragma unroll
        for (int k = 0; k < 32; k++) {
            ull h2 = sH[lb * 33 + k];
            const float4* w4 = (const float4*)&sWg[k * 64 + j0];
            float4 w0 = w4[0], w1 = w4[1];
            a[0] = fma2(h2, bc2(w0.x), a[0]);
            a[1] = fma2(h2, bc2(w0.y), a[1]);
            a[2] = fma2(h2, bc2(w0.z), a[2]);
            a[3] = fma2(h2, bc2(w0.w), a[3]);
            a[4] = fma2(h2, bc2(w1.x), a[4]);
            a[5] = fma2(h2, bc2(w1.y), a[5]);
            a[6] = fma2(h2, bc2(w1.z), a[6]);
            a[7] = fma2(h2, bc2(w1.w), a[7]);
        }
        if (jg < 4) {
            #pragma unroll
            for (int jj = 0; jj < 8; jj++) {
                int kk = j0 + jj;
                float alo, ahi, hlo, hhi;
                upk2(a[jj], alo, ahi);
                upk2(sH[lb * 33 + kk], hlo, hhi);
                sRH[lb * 33 + kk] = pk2(sigmoidf_(alo) * hlo, sigmoidf_(ahi) * hhi);
            }
        } else {
            #pragma unroll
            for (int jj = 0; jj < 8; jj++) {
                int kk = j0 + jj - 32;
                float alo, ahi;
                upk2(a[jj], alo, ahi);
                sU[lb * 33 + kk] = pk2(sigmoidf_(alo), sigmoidf_(ahi));
            }
        }
        __syncthreads();
        // ---- phase 2: candidate recurrence + update + direct output ----
        #pragma unroll
        for (int k = 0; k < 32; k++) {
            ull rh = sRH[lb * 33 + k];
            const float4* w4 = (const float4*)&sWc[k * 32 + jc0];
            float4 w = w4[0];
            c4[0] = fma2(rh, bc2(w.x), c4[0]);
            c4[1] = fma2(rh, bc2(w.y), c4[1]);
            c4[2] = fma2(rh, bc2(w.z), c4[2]);
            c4[3] = fma2(rh, bc2(w.w), c4[3]);
        }
        float f0[4], f1[4];
        #pragma unroll
        for (int jj = 0; jj < 4; jj++) {
            int k = jc0 + jj;
            float clo, chi, ulo, uhi, hlo, hhi;
            upk2(c4[jj], clo, chi);
            clo = tanhf_(clo); chi = tanhf_(chi);
            upk2(sU[lb * 33 + k], ulo, uhi);
            upk2(sH[lb * 33 + k], hlo, hhi);
            float hn0 = ulo * hlo + (1.0f - ulo) * clo;
            float hn1 = uhi * hhi + (1.0f - uhi) * chi;
            sH[lb * 33 + k] = pk2(hn0, hn1);
            f0[jj] = hn0; f1[jj] = hn1;
        }
        float* ob = out + (size_t)b0 * (TT * 64) + t * 64 + ycol + jc0;
        *(float4*)ob = make_float4(f0[0], f0[1], f0[2], f0[3]);
        *(float4*)(ob + TT * 64) = make_float4(f1[0], f1[1], f1[2], f1[3]);
        // store prefetched tile into the other buffer
        float* sYn = sY + (buf ^ 1) * 4096 + prow * 64 + pc0;
        ((float4*)sYn)[0] = p0;
        ((float4*)sYn)[1] = p1;
        ((float4*)sYn)[2] = p2;
        ((float4*)sYn)[3] = p3;
        __syncthreads();
    }
}

// ---------------- launch ----------------
extern "C" void kernel_launch(void* const* d_in, const int* in_sizes, int n_in,
                              void* d_out, int out_size) {
    const int*   tokens_before = (const int*)d_in[0];
    const int*   types_before  = (const int*)d_in[1];
    const void*  mask_before   = d_in[2];
    const int*   tokens_after  = (const int*)d_in[3];
    const int*   types_after   = (const int*)d_in[4];
    const void*  mask_after    = d_in[5];
    const float* token_emb     = (const float*)d_in[6];
    const float* type_emb      = (const float*)d_in[7];
    const float* hole          = (const float*)d_in[8];
    const float* gk_fw0 = (const float*)d_in[9];
    const float* gb_fw0 = (const float*)d_in[10];
    const float* ck_fw0 = (const float*)d_in[11];
    const float* cb_fw0 = (const float*)d_in[12];
    const float* gk_bw0 = (const float*)d_in[13];
    const float* gb_bw0 = (const float*)d_in[14];
    const float* ck_bw0 = (const float*)d_in[15];
    const float* cb_bw0 = (const float*)d_in[16];
    const float* gk_fw1 = (const float*)d_in[17];
    const float* gb_fw1 = (const float*)d_in[18];
    const float* ck_fw1 = (const float*)d_in[19];
    const float* cb_fw1 = (const float*)d_in[20];
    const float* gk_bw1 = (const float*)d_in[21];
    const float* gb_bw1 = (const float*)d_in[22];
    const float* ck_bw1 = (const float*)d_in[23];
    const float* cb_bw1 = (const float*)d_in[24];
    float* out = (float*)d_out;

    float* gx0; cudaGetSymbolAddress((void**)&gx0, g_gx0);
    float* y0;  cudaGetSymbolAddress((void**)&y0,  g_y0);

    cudaFuncSetAttribute(k_scan1f, cudaFuncAttributeMaxDynamicSharedMemorySize, SM1F_BYTES);

    k_detect<<<1, 256>>>((const unsigned char*)mask_before);
    k_typemax<<<dim3(BB / 32, 20), dim3(8, 32)>>>(types_before, mask_before, types_after, mask_after, type_emb);
    k_tokproj<<<VT + 1, 192>>>(token_emb, hole,
                               gk_fw0, gb_fw0, ck_fw0, cb_fw0,
                               gk_bw0, gb_bw0, ck_bw0, cb_bw0);
    k_x0<<<dim3(BB / 64, TT, 2), dim3(32, 8)>>>(tokens_before, tokens_after,
                                                gk_fw0, ck_fw0, gk_bw0, ck_bw0);
    k_scan<<<dim3(BB / 64, 2), dim3(32, 8)>>>(gx0, y0, gk_fw0, ck_fw0, gk_bw0, ck_bw0, 160);
    k_scan1f<<<dim3(BB / 64, 2), dim3(32, 8), SM1F_BYTES>>>(y0, out,
                                                gk_fw1, gb_fw1, ck_fw1, cb_fw1,
                                                gk_bw1, gb_bw1, ck_bw1, cb_bw1);
}